// round 2
// baseline (speedup 1.0000x reference)
#include <cuda_runtime.h>
#include <cuda_bf16.h>

// Problem constants (from reference)
#define BATCHES 8
#define NP 4096
#define STRIDE 4
#define KNN 32
#define NS (NP / STRIDE)          // 1024 samples per batch
#define NSAMP (BATCHES * NS)      // 8192
#define NPTS (BATCHES * NP)       // 32768
#define DIN 64
#define H1DIM 128
#define H2DIM 256

// Output layout (float32 concat of the reference tuple)
#define XOUT_OFF   0
#define POS_OFF    (NSAMP * H2DIM)                 // 2097152
#define BATCH_OFF  (POS_OFF + NSAMP * 3)           // 2121728
#define IDX_OFF    (BATCH_OFF + NSAMP)             // 2129920
#define TOTAL_OUT  (IDX_OFF + NSAMP)               // 2138112

// Scratch (static __device__ arrays: no allocation)
__device__ float g_xw1[NPTS * H1DIM];   // 16 MB: x @ W1[:64]
__device__ int   g_nbr[NSAMP * KNN];    // 1 MB : local neighbor indices

__device__ __forceinline__ unsigned long long umin64(unsigned long long a,
                                                     unsigned long long b) {
    return b < a ? b : a;
}

// packed fp32x2 FMA (sm_100+): two independent fp32 FMAs per instruction
__device__ __forceinline__ void fma2(unsigned long long& a, unsigned long long x,
                                     unsigned long long w) {
    asm("fma.rn.f32x2 %0, %1, %2, %0;" : "+l"(a) : "l"(x), "l"(w));
}
__device__ __forceinline__ float red2(unsigned long long a, float bias) {
    float lo, hi;
    asm("mov.b64 {%0, %1}, %2;" : "=f"(lo), "=f"(hi) : "l"(a));
    return lo + hi + bias;
}

// ---------------------------------------------------------------------------
// Kernel 1: xw1[n][j] = sum_f x[n][f] * W1[f][j]   (f < 64)
// ---------------------------------------------------------------------------
__global__ void __launch_bounds__(128) k_xw1(const float* __restrict__ x,
                                             const float* __restrict__ W1) {
    __shared__ float xs[8 * DIN];
    const int p0 = blockIdx.x * 8;
    const int tid = threadIdx.x;   // 128, tid == output channel j
    for (int i = tid; i < 8 * DIN; i += 128) xs[i] = x[p0 * DIN + i];
    __syncthreads();

    float acc[8];
#pragma unroll
    for (int p = 0; p < 8; ++p) acc[p] = 0.f;
#pragma unroll
    for (int f = 0; f < DIN; ++f) {
        float w = W1[f * H1DIM + tid];
#pragma unroll
        for (int p = 0; p < 8; ++p) acc[p] = fmaf(xs[p * DIN + f], w, acc[p]);
    }
#pragma unroll
    for (int p = 0; p < 8; ++p) g_xw1[(p0 + p) * H1DIM + tid] = acc[p];
}

// ---------------------------------------------------------------------------
// Kernel 2: KNN v2. One block (256 threads) = 16 samples of one batch.
// Phase 1: each WARP selects its own top-32 of its 512 points via 32 rounds
//          of warp argmin (u64 flipped-d2|idx keys in regs, no barriers).
// Phase 2: one warp merges the 8 sorted 32-lists (256 keys), overlapped with
//          the next sample's phase 1 via a double-buffered smem area.
// d2 arithmetic is bit-identical to the round-1 kernel (passed at 7.4e-4).
// ---------------------------------------------------------------------------
#define SPB2 16

__global__ void __launch_bounds__(256) k_knn(const float* __restrict__ pos) {
    extern __shared__ float sm[];
    float* px = sm;
    float* py = sm + NP;
    float* pz = sm + 2 * NP;
    unsigned long long* mbuf = (unsigned long long*)(sm + 3 * NP);  // [2][256]

    const int tid  = threadIdx.x;
    const int lane = tid & 31;
    const int wid  = tid >> 5;
    const int blk  = blockIdx.x;             // 512
    const int b    = blk / (NS / SPB2);
    const int grp  = blk % (NS / SPB2);

    for (int i = tid; i < NP; i += 256) {
        px[i] = pos[(b * NP + i) * 3 + 0];
        py[i] = pos[(b * NP + i) * 3 + 1];
        pz[i] = pos[(b * NP + i) * 3 + 2];
    }
    __syncthreads();

    for (int si = 0; si < SPB2; ++si) {
        const int s_local = grp * SPB2 + si;
        const int c_local = s_local * STRIDE;
        const float ax = px[c_local], ay = py[c_local], az = pz[c_local];
        const float as2 = __fadd_rn(__fadd_rn(__fmul_rn(ax, ax), __fmul_rn(ay, ay)),
                                    __fmul_rn(az, az));

        unsigned long long keys[16];
#pragma unroll
        for (int t = 0; t < 16; ++t) {
            const int i = tid + t * 256;
            const float bx = px[i], by = py[i], bz = pz[i];
            const float bn2 = __fadd_rn(__fadd_rn(__fmul_rn(bx, bx), __fmul_rn(by, by)),
                                        __fmul_rn(bz, bz));
            const float dot = __fadd_rn(__fadd_rn(__fmul_rn(ax, bx), __fmul_rn(ay, by)),
                                        __fmul_rn(az, bz));
            const float d2  = __fadd_rn(__fadd_rn(as2, bn2), -__fmul_rn(2.0f, dot));
            unsigned u = __float_as_uint(d2);
            unsigned kk = (u & 0x80000000u) ? ~u : (u | 0x80000000u);
            keys[t] = (((unsigned long long)kk) << 32) | (unsigned)i;
        }
        unsigned long long lmin = keys[0];
#pragma unroll
        for (int t = 1; t < 16; ++t) lmin = umin64(lmin, keys[t]);

        // Phase 1: warp-local top-32 (ascending), no barriers.
        unsigned long long mywin = 0;
        for (int r = 0; r < KNN; ++r) {
            unsigned long long w = lmin;
#pragma unroll
            for (int o = 16; o > 0; o >>= 1) {
                unsigned long long v = __shfl_xor_sync(0xffffffffu, w, o);
                w = umin64(w, v);
            }
            if (lane == r) mywin = w;
            if (lmin == w) {   // unique owner (idx embedded in key)
#pragma unroll
                for (int t = 0; t < 16; ++t)
                    if (keys[t] == w) keys[t] = 0xffffffffffffffffull;
                lmin = keys[0];
#pragma unroll
                for (int t = 1; t < 16; ++t) lmin = umin64(lmin, keys[t]);
            }
        }
        mbuf[(si & 1) * 256 + wid * 32 + lane] = mywin;
        __syncthreads();

        // Phase 2: warp (si & 7) merges; other warps go start next sample.
        if (wid == (si & 7)) {
            const int sidx = b * NS + s_local;
            unsigned long long mk[8];
#pragma unroll
            for (int t = 0; t < 8; ++t) mk[t] = mbuf[(si & 1) * 256 + lane + 32 * t];
            unsigned long long lm2 = mk[0];
#pragma unroll
            for (int t = 1; t < 8; ++t) lm2 = umin64(lm2, mk[t]);
            for (int r = 0; r < KNN; ++r) {
                unsigned long long w = lm2;
#pragma unroll
                for (int o = 16; o > 0; o >>= 1) {
                    unsigned long long v = __shfl_xor_sync(0xffffffffu, w, o);
                    w = umin64(w, v);
                }
                if (lane == r) g_nbr[sidx * KNN + r] = (int)(unsigned)(w & 0xffffffffull);
                if (lm2 == w) {
#pragma unroll
                    for (int t = 0; t < 8; ++t)
                        if (mk[t] == w) mk[t] = 0xffffffffffffffffull;
                    lm2 = mk[0];
#pragma unroll
                    for (int t = 1; t < 8; ++t) lm2 = umin64(lm2, mk[t]);
                }
            }
        }
    }
}

// ---------------------------------------------------------------------------
// Kernel 3: MLP + max-pool with packed f32x2 FMAs.
// One block = 4 samples, 256 threads = 256 output channels. W2 column lives
// in 64 packed u64 registers. All 32 h1 vectors of a sample are produced in
// smem up front (1 sync), then consumed 4 neighbors at a time with 4
// independent f32x2 accumulator chains.
// ---------------------------------------------------------------------------
#define SPB3 4

__global__ void __launch_bounds__(256, 1) k_mlp(const float* __restrict__ pos,
                                                const float* __restrict__ W1,
                                                const float* __restrict__ b1,
                                                const float* __restrict__ W2,
                                                const float* __restrict__ b2,
                                                float* __restrict__ out,
                                                int write_extras) {
    __shared__ __align__(16) float h1s[KNN][H1DIM];   // 16 KB
    __shared__ float w1r[3][H1DIM];
    __shared__ float b1s[H1DIM];
    __shared__ float npx[KNN], npy[KNN], npz[KNN];
    __shared__ int   gix[KNN];

    const int tid = threadIdx.x;       // 256, tid == output channel c
    const int blk = blockIdx.x;        // NSAMP/SPB3 = 2048

    if (tid < H1DIM) {
        w1r[0][tid] = W1[64 * H1DIM + tid];
        w1r[1][tid] = W1[65 * H1DIM + tid];
        w1r[2][tid] = W1[66 * H1DIM + tid];
        b1s[tid]    = b1[tid];
    }
    // Pack this thread's W2 column as 64 f32x2 pairs (adjacent j).
    unsigned long long w2p[64];
#pragma unroll
    for (int q = 0; q < 64; ++q) {
        float w0 = W2[(2 * q) * H2DIM + tid];
        float w1v = W2[(2 * q + 1) * H2DIM + tid];
        asm("mov.b64 %0, {%1, %2};" : "=l"(w2p[q]) : "f"(w0), "f"(w1v));
    }
    const float b2c = b2[tid];
    const int j    = tid & 127;
    const int half = tid >> 7;
    __syncthreads();

    for (int si = 0; si < SPB3; ++si) {
        const int s       = blk * SPB3 + si;
        const int b       = s >> 10;            // / NS
        const int s_local = s & (NS - 1);
        const int p       = b * NP + s_local * STRIDE;
        const float psx = pos[3 * p], psy = pos[3 * p + 1], psz = pos[3 * p + 2];

        if (tid < KNN) {
            int nl = g_nbr[s * KNN + tid];
            int g  = b * NP + nl;
            gix[tid] = g;
            npx[tid] = pos[3 * g];
            npy[tid] = pos[3 * g + 1];
            npz[tid] = pos[3 * g + 2];
        }
        __syncthreads();

        // Produce all 32 h1 vectors (each thread makes 16 values).
#pragma unroll
        for (int kk = 0; kk < 16; ++kk) {
            const int k = kk * 2 + half;
            const int g = gix[k];
            float rx = npx[k] - psx;
            float ry = npy[k] - psy;
            float rz = npz[k] - psz;
            float v = g_xw1[g * H1DIM + j];
            v = fmaf(rx, w1r[0][j], v);
            v = fmaf(ry, w1r[1][j], v);
            v = fmaf(rz, w1r[2][j], v);
            v += b1s[j];
            h1s[k][j] = fmaxf(v, 0.f);
        }
        __syncthreads();

        // Consume: 4 neighbors per iteration, 4 independent f32x2 chains.
        float amax = -3.402823466e38f;
#pragma unroll
        for (int kq = 0; kq < 8; ++kq) {
            const ulonglong2* h0 = (const ulonglong2*)h1s[4 * kq + 0];
            const ulonglong2* h1 = (const ulonglong2*)h1s[4 * kq + 1];
            const ulonglong2* h2 = (const ulonglong2*)h1s[4 * kq + 2];
            const ulonglong2* h3 = (const ulonglong2*)h1s[4 * kq + 3];
            unsigned long long a0 = 0, a1 = 0, a2 = 0, a3 = 0;
#pragma unroll
            for (int q = 0; q < 32; ++q) {
                const ulonglong2 v0 = h0[q];
                const ulonglong2 v1 = h1[q];
                const ulonglong2 v2 = h2[q];
                const ulonglong2 v3 = h3[q];
                fma2(a0, v0.x, w2p[2 * q]); fma2(a0, v0.y, w2p[2 * q + 1]);
                fma2(a1, v1.x, w2p[2 * q]); fma2(a1, v1.y, w2p[2 * q + 1]);
                fma2(a2, v2.x, w2p[2 * q]); fma2(a2, v2.y, w2p[2 * q + 1]);
                fma2(a3, v3.x, w2p[2 * q]); fma2(a3, v3.y, w2p[2 * q + 1]);
            }
            amax = fmaxf(amax, fmaxf(red2(a0, b2c), 0.f));
            amax = fmaxf(amax, fmaxf(red2(a1, b2c), 0.f));
            amax = fmaxf(amax, fmaxf(red2(a2, b2c), 0.f));
            amax = fmaxf(amax, fmaxf(red2(a3, b2c), 0.f));
        }
        out[XOUT_OFF + s * H2DIM + tid] = amax;
        if (write_extras) {
            if (tid < 3)  out[POS_OFF + s * 3 + tid] = pos[3 * p + tid];
            if (tid == 3) out[BATCH_OFF + s] = (float)b;
            if (tid == 4) out[IDX_OFF + s]   = (float)p;
        }
        __syncthreads();   // h1s/npx reused next sample
    }
}

// ---------------------------------------------------------------------------
extern "C" void kernel_launch(void* const* d_in, const int* in_sizes, int n_in,
                              void* d_out, int out_size) {
    const float* x   = (const float*)d_in[0];
    const float* pos = (const float*)d_in[1];
    // d_in[2] = batch (int64), derivable -> unused
    const float* W1  = (const float*)d_in[3];
    const float* b1  = (const float*)d_in[4];
    const float* W2  = (const float*)d_in[5];
    const float* b2  = (const float*)d_in[6];
    float* out = (float*)d_out;

    const int write_extras = (out_size >= TOTAL_OUT) ? 1 : 0;

    k_xw1<<<NPTS / 8, 128>>>(x, W1);

    const int smem2 = (3 * NP) * (int)sizeof(float) + 2 * 256 * (int)sizeof(unsigned long long);
    cudaFuncSetAttribute(k_knn, cudaFuncAttributeMaxDynamicSharedMemorySize, smem2);
    k_knn<<<BATCHES * (NS / SPB2), 256, smem2>>>(pos);

    k_mlp<<<NSAMP / SPB3, 256>>>(pos, W1, b1, W2, b2, out, write_extras);
}